// round 16
// baseline (speedup 1.0000x reference)
#include <cuda_runtime.h>
#include <cuda_fp16.h>
#include <cstddef>
#include <cstdint>

#define IDIM 256
#define JDIM 256
#define CDIM 256
#define HDIM 8
#define DDIM 64
#define HD   512    // H*D
#define NROW 65536  // I*J

// ---------------- device-global scratch (no allocations allowed) ----------------
__device__ __half g_xn[(size_t)NROW * CDIM];   // layernormed x (fp16)
__device__ __half g_q [(size_t)NROW * HD];     // fp16, pre-scaled by 1/8
__device__ __half g_k [(size_t)NROW * HD];     // fp16
__device__ __half g_v [(size_t)NROW * HD];     // fp16
__device__ __half g_g [(size_t)NROW * HD];     // raw gate projection (fp16)
__device__ __half g_o [(size_t)NROW * HD];     // gated attention output (fp16)
// fp16, transposed weights
__device__ __half g_wT [4 * HD * CDIM];        // [2048][256]  rows: Wq|Wk|Wv|Wg
__device__ __half g_woT[CDIM * HD];            // [256][512]

// ---------------- fp16 mma / ldsm / cp.async helpers ----------------
__device__ __forceinline__ void mma_f16(float* c, const unsigned* a, unsigned b0, unsigned b1) {
    asm volatile(
        "mma.sync.aligned.m16n8k16.row.col.f32.f16.f16.f32 "
        "{%0,%1,%2,%3}, {%4,%5,%6,%7}, {%8,%9}, {%0,%1,%2,%3};"
        : "+f"(c[0]), "+f"(c[1]), "+f"(c[2]), "+f"(c[3])
        : "r"(a[0]), "r"(a[1]), "r"(a[2]), "r"(a[3]), "r"(b0), "r"(b1));
}
__device__ __forceinline__ void ldsm4(unsigned* r, uint32_t addr) {
    asm volatile("ldmatrix.sync.aligned.m8n8.x4.shared.b16 {%0,%1,%2,%3}, [%4];"
                 : "=r"(r[0]), "=r"(r[1]), "=r"(r[2]), "=r"(r[3]) : "r"(addr));
}
__device__ __forceinline__ void ldsm4t(unsigned* r, uint32_t addr) {
    asm volatile("ldmatrix.sync.aligned.m8n8.x4.trans.shared.b16 {%0,%1,%2,%3}, [%4];"
                 : "=r"(r[0]), "=r"(r[1]), "=r"(r[2]), "=r"(r[3]) : "r"(addr));
}
__device__ __forceinline__ void cpa16(uint32_t dst, const void* src) {
    asm volatile("cp.async.cg.shared.global [%0], [%1], 16;" :: "r"(dst), "l"(src));
}
__device__ __forceinline__ void cpa_commit() { asm volatile("cp.async.commit_group;"); }
__device__ __forceinline__ unsigned f22h(float lo, float hi) {
    __half2 h = __floats2half2_rn(lo, hi);
    return *(unsigned*)&h;
}

// ============================= weight transpose->fp16 prepass ==============================
__global__ void wtrans4(const float* __restrict__ Wq, const float* __restrict__ Wk,
                        const float* __restrict__ Wv, const float* __restrict__ Wg,
                        __half* __restrict__ wT) {
    __shared__ float t[32][33];
    const float* W = (blockIdx.z == 0) ? Wq : (blockIdx.z == 1) ? Wk
                   : (blockIdx.z == 2) ? Wv : Wg;
    __half* WT = wT + (size_t)blockIdx.z * HD * CDIM;
    int n0 = blockIdx.x * 32, k0 = blockIdx.y * 32;
    for (int i = threadIdx.y; i < 32; i += 8)
        t[i][threadIdx.x] = W[(size_t)(k0 + i) * HD + n0 + threadIdx.x];
    __syncthreads();
    for (int i = threadIdx.y; i < 32; i += 8)
        WT[(size_t)(n0 + i) * CDIM + k0 + threadIdx.x] = __float2half_rn(t[threadIdx.x][i]);
}

__global__ void wtrans(const float* __restrict__ W, __half* __restrict__ WT, int K, int N) {
    __shared__ float t[32][33];
    int n0 = blockIdx.x * 32, k0 = blockIdx.y * 32;
    for (int i = threadIdx.y; i < 32; i += 8)
        t[i][threadIdx.x] = W[(size_t)(k0 + i) * N + n0 + threadIdx.x];
    __syncthreads();
    for (int i = threadIdx.y; i < 32; i += 8)
        WT[(size_t)(n0 + i) * K + k0 + threadIdx.x] = __float2half_rn(t[threadIdx.x][i]);
}

// ============================= LayerNorm (warp-per-row, fp16 output) ==============================
__global__ void ln_kernel(const float* __restrict__ x,
                          const float* __restrict__ gamma,
                          const float* __restrict__ beta) {
    const int warp = threadIdx.x >> 5;
    const int lane = threadIdx.x & 31;
    const int row  = blockIdx.x * 8 + warp;
    const float* xr = x + (size_t)row * CDIM;

    float4 v0 = *(const float4*)(xr + lane * 4);
    float4 v1 = *(const float4*)(xr + 128 + lane * 4);

    float s = (v0.x + v0.y) + (v0.z + v0.w) + (v1.x + v1.y) + (v1.z + v1.w);
    #pragma unroll
    for (int o = 16; o > 0; o >>= 1) s += __shfl_xor_sync(0xffffffffu, s, o);
    float mean = s * (1.0f / CDIM);

    float d0x = v0.x - mean, d0y = v0.y - mean, d0z = v0.z - mean, d0w = v0.w - mean;
    float d1x = v1.x - mean, d1y = v1.y - mean, d1z = v1.z - mean, d1w = v1.w - mean;
    float s2 = d0x*d0x + d0y*d0y + d0z*d0z + d0w*d0w
             + d1x*d1x + d1y*d1y + d1z*d1z + d1w*d1w;
    #pragma unroll
    for (int o = 16; o > 0; o >>= 1) s2 += __shfl_xor_sync(0xffffffffu, s2, o);
    float rstd = rsqrtf(s2 * (1.0f / CDIM) + 1e-5f);

    float4 ga0 = *(const float4*)(gamma + lane * 4);
    float4 ga1 = *(const float4*)(gamma + 128 + lane * 4);
    float4 be0 = *(const float4*)(beta + lane * 4);
    float4 be1 = *(const float4*)(beta + 128 + lane * 4);

    __half* outr = g_xn + (size_t)row * CDIM;
    uint2 o0, o1;
    o0.x = f22h(d0x * rstd * ga0.x + be0.x, d0y * rstd * ga0.y + be0.y);
    o0.y = f22h(d0z * rstd * ga0.z + be0.z, d0w * rstd * ga0.w + be0.w);
    o1.x = f22h(d1x * rstd * ga1.x + be1.x, d1y * rstd * ga1.y + be1.y);
    o1.y = f22h(d1z * rstd * ga1.z + be1.z, d1w * rstd * ga1.w + be1.w);
    *(uint2*)(outr + lane * 4) = o0;
    *(uint2*)(outr + 128 + lane * 4) = o1;
}

// ============================= FP16 tensor-core GEMM (wide warp tile) ==============================
// Block 128x256, 8 warps (2x4), warp tile 64x64: 8 ldsm4 -> 32 MMA per k16 step
// (operand:compute ratio 4, was 2.67). 1 CTA/SM (~190 regs), 3-stage cp.async,
// dynamic smem (90 KB). k-chunk 32 halves.
// mode 0: fused QKVG (A=g_xn, BT=g_wT); Q scaled 1/8; all outputs fp16.
// mode 1: output proj (A=g_o, BT=g_woT, C=float out + bias).
#define ASTRH 40                           // 32 k-halves + 8 pad (80B row stride)
#define A_STAGE_H (128 * ASTRH)            // 5120 halves
#define B_STAGE_H (256 * ASTRH)            // 10240 halves
#define GEMM_SMEM_BYTES (3 * (A_STAGE_H + B_STAGE_H) * 2)   // 92160 B

__global__ void __launch_bounds__(256, 1) gemm_fp16(
    const __half* __restrict__ BT, const float* __restrict__ bias,
    float* __restrict__ Cext, int mode, int K, int ldc) {

    extern __shared__ __half smem[];
    __half* sA = smem;                       // [3][128][ASTRH]
    __half* sB = smem + 3 * A_STAGE_H;       // [3][256][ASTRH]

    const int tid  = threadIdx.x;
    const int warp = tid >> 5;
    const int lane = tid & 31;
    const int lg   = lane >> 2;
    const int lq   = lane & 3;
    const int wm   = warp >> 2;              // 0..1  (64-row tiles)
    const int wn   = warp & 3;               // 0..3  (64-col tiles)
    const int m0   = blockIdx.y * 128;
    const int n0bt = blockIdx.x * 256;

    const __half* A;
    __half* Ch = nullptr;
    float*  Cf = nullptr;
    int n0c;
    float scale = 1.0f;
    if (mode == 0) {
        A = g_xn;
        int which = n0bt >> 9;
        if (which == 0)      { Ch = g_q; scale = 0.125f; }
        else if (which == 1) { Ch = g_k; }
        else if (which == 2) { Ch = g_v; }
        else                 { Ch = g_g; }
        n0c = n0bt & 511;
    } else {
        A = g_o;
        Cf = Cext;
        n0c = n0bt;
    }

    const uint32_t sAb = (uint32_t)__cvta_generic_to_shared(sA);
    const uint32_t sBb = (uint32_t)__cvta_generic_to_shared(sB);
    const uint32_t aStB = A_STAGE_H * 2u;
    const uint32_t bStB = B_STAGE_H * 2u;

    const int rA = (lane & 7) + ((lane >> 3) & 1) * 8;
    const int cA = (lane >> 4) & 1;
    const int rB = (lane & 7) + ((lane >> 4) & 1) * 8;
    const int cB = (lane >> 3) & 1;

    float acc[4][8][4];
    #pragma unroll
    for (int i = 0; i < 4; i++)
        #pragma unroll
        for (int j = 0; j < 8; j++)
            #pragma unroll
            for (int e = 0; e < 4; e++) acc[i][j][e] = 0.f;

    const int KT = K >> 5;                   // k-chunks of 32 halves
    const int cprow = tid >> 2;              // 0..63
    const int cpc   = tid & 3;               // 16B chunk within 64B row

    // ---- prologue: stages 0,1 ----
    #pragma unroll
    for (int s = 0; s < 2; s++) {
        int koff = s * 32;
        #pragma unroll
        for (int i = 0; i < 2; i++) {        // A: 128 rows
            int r = i * 64 + cprow;
            cpa16(sAb + s * aStB + (uint32_t)(r * ASTRH + cpc * 8) * 2,
                  A + (size_t)(m0 + r) * K + koff + cpc * 8);
        }
        #pragma unroll
        for (int i = 0; i < 4; i++) {        // B: 256 rows
            int r = i * 64 + cprow;
            cpa16(sBb + s * bStB + (uint32_t)(r * ASTRH + cpc * 8) * 2,
                  BT + (size_t)(n0bt + r) * K + koff + cpc * 8);
        }
        cpa_commit();
    }

    for (int kt = 0; kt < KT; kt++) {
        if (kt + 1 < KT) { asm volatile("cp.async.wait_group 1;"); }
        else             { asm volatile("cp.async.wait_group 0;"); }
        __syncthreads();

        if (kt + 2 < KT) {
            int s = (kt + 2) % 3;
            int koff = (kt + 2) * 32;
            #pragma unroll
            for (int i = 0; i < 2; i++) {
                int r = i * 64 + cprow;
                cpa16(sAb + s * aStB + (uint32_t)(r * ASTRH + cpc * 8) * 2,
                      A + (size_t)(m0 + r) * K + koff + cpc * 8);
            }
            #pragma unroll
            for (int i = 0; i < 4; i++) {
                int r = i * 64 + cprow;
                cpa16(sBb + s * bStB + (uint32_t)(r * ASTRH + cpc * 8) * 2,
                      BT + (size_t)(n0bt + r) * K + koff + cpc * 8);
            }
            cpa_commit();
        }

        const uint32_t aS = sAb + (uint32_t)(kt % 3) * aStB;
        const uint32_t bS = sBb + (uint32_t)(kt % 3) * bStB;
        #pragma unroll
        for (int ks = 0; ks < 2; ks++) {     // two k16 steps per chunk
            unsigned a[4][4], b[4][4];
            #pragma unroll
            for (int p = 0; p < 4; p++) {    // B: 64 cols = 4 ldsm4
                int row = wn * 64 + p * 16 + rB;
                ldsm4(b[p], bS + (uint32_t)(row * ASTRH + (ks * 2 + cB) * 8) * 2);
            }
            #pragma unroll
            for (int mf = 0; mf < 4; mf++) { // A: 64 rows = 4 ldsm4
                int row = wm * 64 + mf * 16 + rA;
                ldsm4(a[mf], aS + (uint32_t)(row * ASTRH + (ks * 2 + cA) * 8) * 2);
            }
            #pragma unroll
            for (int mf = 0; mf < 4; mf++)
                #pragma unroll
                for (int nf = 0; nf < 8; nf++)
                    mma_f16(acc[mf][nf], a[mf],
                            b[nf >> 1][(nf & 1) * 2], b[nf >> 1][(nf & 1) * 2 + 1]);
        }
    }

    // ---- epilogue ----
    #pragma unroll
    for (int mf = 0; mf < 4; mf++) {
        int row = m0 + wm * 64 + mf * 16 + lg;
        #pragma unroll
        for (int nf = 0; nf < 8; nf++) {
            int col = n0c + wn * 64 + nf * 8 + 2 * lq;
            if (Ch) {
                *(unsigned*)&Ch[(size_t)row * ldc + col] =
                    f22h(acc[mf][nf][0] * scale, acc[mf][nf][1] * scale);
                *(unsigned*)&Ch[(size_t)(row + 8) * ldc + col] =
                    f22h(acc[mf][nf][2] * scale, acc[mf][nf][3] * scale);
            } else {
                float b0 = bias ? bias[col] : 0.f;
                float b1 = bias ? bias[col + 1] : 0.f;
                float2 v0, v1;
                v0.x = acc[mf][nf][0] + b0; v0.y = acc[mf][nf][1] + b1;
                v1.x = acc[mf][nf][2] + b0; v1.y = acc[mf][nf][3] + b1;
                *(float2*)&Cf[(size_t)row * ldc + col] = v0;
                *(float2*)&Cf[(size_t)(row + 8) * ldc + col] = v1;
            }
        }
    }
}

// ============================= FP16 flash attention + gate (register-direct P) ==============================
// 512 threads = 16 warps, 16 query rows/warp. P stays in registers: the S
// C-fragment (rows {lg,lg+8} x cols {2lq,2lq+1}) packs directly into the PV
// A-fragment (k16). No Ps smem, no mainloop syncs. V B-frags via ldmatrix.trans.
// Single-pass softmax (scores O(6); masked -> exp(-1e9)=0).
#define KSH 72
#define BIAS_OFFH (2 * 256 * KSH)
#define ATTN_SMEM_BYTES (BIAS_OFFH * 2 + 256 * 4)    // ~74.8 KB

__global__ void __launch_bounds__(512, 1) attn_fp16(const float* __restrict__ mask,
                                                    const float* __restrict__ bg) {
    extern __shared__ __half shh[];
    __half* Ks = shh;                    // [256][72]
    __half* Vs = shh + 256 * KSH;        // [256][72]
    float* bias_s = (float*)(shh + BIAS_OFFH);   // [256]

    const int h    = blockIdx.x;
    const int i    = blockIdx.y;
    const int tid  = threadIdx.x;
    const int warp = tid >> 5;
    const int lane = tid & 31;
    const int lq   = lane & 3;
    const int lg   = lane >> 2;
    const size_t base = ((size_t)i * 256) * HD + h * 64;

    const uint32_t shb = (uint32_t)__cvta_generic_to_shared(shh);
    const uint32_t KsB = shb;
    const uint32_t VsB = shb + 256 * KSH * 2u;

    const int rB = (lane & 7) + ((lane >> 4) & 1) * 8;
    const int cB = (lane >> 3) & 1;

    // ---- K,V tile copies (row = 64 halves = 8 uint4) ----
    for (int idx = tid; idx < 256 * 8; idx += 512) {
        int r  = idx >> 3;
        int c8 = (idx & 7) * 8;
        *(uint4*)&Ks[r * KSH + c8] = *(const uint4*)&g_k[base + (size_t)r * HD + c8];
        *(uint4*)&Vs[r * KSH + c8] = *(const uint4*)&g_v[base + (size_t)r * HD + c8];
    }
    if (tid < 256) bias_s[tid] = 1e9f * (mask[i * 256 + tid] - 1.0f);
    __syncthreads();

    // ---- Q fragments (g_q already scaled by 1/8): 4 k16-frags ----
    const int row0 = warp * 16 + lg;
    unsigned qa[4][4];
    #pragma unroll
    for (int kf = 0; kf < 4; kf++) {
        int col = kf * 16 + 2 * lq;
        qa[kf][0] = *(const unsigned*)&g_q[base + (size_t)row0 * HD + col];
        qa[kf][1] = *(const unsigned*)&g_q[base + (size_t)(row0 + 8) * HD + col];
        qa[kf][2] = *(const unsigned*)&g_q[base + (size_t)row0 * HD + col + 8];
        qa[kf][3] = *(const unsigned*)&g_q[base + (size_t)(row0 + 8) * HD + col + 8];
    }

    float oc[8][4];
    #pragma unroll
    for (int nf = 0; nf < 8; nf++)
        #pragma unroll
        for (int e = 0; e < 4; e++) oc[nf][e] = 0.f;

    float l0 = 0.f, l1 = 0.f;

    for (int kc = 0; kc < 256; kc += 64) {
        // ---- S = Q @ K^T chunk [16 x 64] ----
        float sc[8][4];
        #pragma unroll
        for (int nf = 0; nf < 8; nf++)
            sc[nf][0] = sc[nf][1] = sc[nf][2] = sc[nf][3] = 0.f;

        #pragma unroll
        for (int kb = 0; kb < 4; kb++) {          // d16 per step
            unsigned bk[4][4];
            #pragma unroll
            for (int p = 0; p < 4; p++) {         // 16 keys each
                int key = kc + p * 16 + rB;
                ldsm4(bk[p], KsB + (uint32_t)(key * KSH + (kb * 2 + cB) * 8) * 2);
            }
            #pragma unroll
            for (int nf = 0; nf < 8; nf++)
                mma_f16(sc[nf], qa[kb],
                        bk[nf >> 1][(nf & 1) * 2], bk[nf >> 1][(nf & 1) * 2 + 1]);
        }

        // ---- p = exp(s + bias) in-place; accumulate l ----
        #pragma unroll
        for (int nf = 0; nf < 8; nf++) {
            float bb0 = bias_s[kc + nf * 8 + 2 * lq];
            float bb1 = bias_s[kc + nf * 8 + 2 * lq + 1];
            sc[nf][0] = __expf(sc[nf][0] + bb0);
            sc[nf][1] = __expf(sc[nf][1] + bb1);
            sc[nf][2] = __expf(sc[nf][2] + bb0);
            sc[nf][3] = __expf(sc[nf][3] + bb1);
            l0 += sc[nf][0] + sc[nf][1];
            l1 += sc[nf][2] + sc[nf][3];
        }

        // ---- O += P @ V chunk; P packed register-direct into A-frags ----
        #pragma unroll
        for (int kb = 0; kb < 4; kb++) {          // 16 keys per step
            unsigned pa[4];
            pa[0] = f22h(sc[2 * kb][0],     sc[2 * kb][1]);      // row lg,   keys +2lq
            pa[1] = f22h(sc[2 * kb][2],     sc[2 * kb][3]);      // row lg+8
            pa[2] = f22h(sc[2 * kb + 1][0], sc[2 * kb + 1][1]);  // row lg,   keys +8+2lq
            pa[3] = f22h(sc[2 * kb + 1][2], sc[2 * kb + 1][3]);  // row lg+8
            #pragma unroll
            for (int p = 0; p < 4; p++) {         // d16 per step
                unsigned bv[4];
                int keyrow = kc + kb * 16 + rB;
                ldsm4t(bv, VsB + (uint32_t)(keyrow * KSH + (p * 2 + cB) * 8) * 2);
                mma_f16(oc[2 * p],     pa, bv[0], bv[2]);
                mma_f16(oc[2 * p + 1], pa, bv[1], bv[3]);
            }
        }
    }

    // ---- row sums across the 4-lane groups ----
    l0 += __shfl_xor_sync(0xffffffffu, l0, 1);
    l0 += __shfl_xor_sync(0xffffffffu, l0, 2);
    l1 += __shfl_xor_sync(0xffffffffu, l1, 1);
    l1 += __shfl_xor_sync(0xffffffffu, l1, 2);

    float inv0 = 1.0f / l0, inv1 = 1.0f / l1;
    #pragma unroll
    for (int nf = 0; nf < 8; nf++) {
        int d = nf * 8 + 2 * lq;
        float bg0 = bg[h * 64 + d], bg1 = bg[h * 64 + d + 1];
        size_t a0 = base + (size_t)row0 * HD + d;
        size_t a1 = base + (size_t)(row0 + 8) * HD + d;
        __half2 gh0 = *(const __half2*)&g_g[a0];
        __half2 gh1 = *(const __half2*)&g_g[a1];
        float2 gv0 = __half22float2(gh0);
        float2 gv1 = __half22float2(gh1);
        float o0x = oc[nf][0] * inv0 * (1.0f / (1.0f + __expf(-(gv0.x + bg0))));
        float o0y = oc[nf][1] * inv0 * (1.0f / (1.0f + __expf(-(gv0.y + bg1))));
        float o1x = oc[nf][2] * inv1 * (1.0f / (1.0f + __expf(-(gv1.x + bg0))));
        float o1y = oc[nf][3] * inv1 * (1.0f / (1.0f + __expf(-(gv1.y + bg1))));
        *(unsigned*)&g_o[a0] = f22h(o0x, o0y);
        *(unsigned*)&g_o[a1] = f22h(o1x, o1y);
    }
}

// ============================= launch ==============================
extern "C" void kernel_launch(void* const* d_in, const int* in_sizes, int n_in,
                              void* d_out, int out_size) {
    const float* x     = (const float*)d_in[0];
    const float* mask  = (const float*)d_in[1];
    const float* gamma = (const float*)d_in[2];
    const float* beta  = (const float*)d_in[3];
    const float* Wq    = (const float*)d_in[4];
    const float* Wk    = (const float*)d_in[5];
    const float* Wv    = (const float*)d_in[6];
    const float* Wg    = (const float*)d_in[7];
    const float* bg    = (const float*)d_in[8];
    const float* Wo    = (const float*)d_in[9];
    const float* bo    = (const float*)d_in[10];
    float* out = (float*)d_out;

    cudaFuncSetAttribute(attn_fp16, cudaFuncAttributeMaxDynamicSharedMemorySize,
                         ATTN_SMEM_BYTES);   // ~74.8 KB
    cudaFuncSetAttribute(gemm_fp16, cudaFuncAttributeMaxDynamicSharedMemorySize,
                         GEMM_SMEM_BYTES);   // ~90 KB

    __half* wT;  cudaGetSymbolAddress((void**)&wT,  g_wT);
    __half* woT; cudaGetSymbolAddress((void**)&woT, g_woT);

    // 0) weight transpose->fp16 prepass
    dim3 tt(32, 8);
    wtrans4<<<dim3(HD / 32, CDIM / 32, 4), tt>>>(Wq, Wk, Wv, Wg, wT);
    wtrans<<<dim3(CDIM / 32, HD / 32), tt>>>(Wo, woT, HD, CDIM);

    // 1) LayerNorm (warp-per-row, fp16 out)
    ln_kernel<<<NROW / 8, 256>>>(x, gamma, beta);

    // 2) fused projections: [Q|K|V|G] = xn @ W  (M=65536, N=2048, K=256)
    gemm_fp16<<<dim3(8, 512), 256, GEMM_SMEM_BYTES>>>(wT, nullptr, nullptr, 0, CDIM, HD);

    // 3) attention + gate per (h, i)
    attn_fp16<<<dim3(HDIM, IDIM), 512, ATTN_SMEM_BYTES>>>(mask, bg);

    // 4) output projection: out = o @ Wo + bo  (M=65536, N=256, K=512)
    gemm_fp16<<<dim3(1, 512), 256, GEMM_SMEM_BYTES>>>(woT, bo, out, 1, HD, CDIM);
}

// round 17
// speedup vs baseline: 1.1026x; 1.1026x over previous
#include <cuda_runtime.h>
#include <cuda_fp16.h>
#include <cstddef>
#include <cstdint>

#define IDIM 256
#define JDIM 256
#define CDIM 256
#define HDIM 8
#define DDIM 64
#define HD   512    // H*D
#define NROW 65536  // I*J

// ---------------- device-global scratch (no allocations allowed) ----------------
__device__ __half g_xn[(size_t)NROW * CDIM];   // layernormed x (fp16)
__device__ __half g_q [(size_t)NROW * HD];     // fp16, pre-scaled by 1/8
__device__ __half g_k [(size_t)NROW * HD];     // fp16
__device__ __half g_v [(size_t)NROW * HD];     // fp16
__device__ __half g_g [(size_t)NROW * HD];     // raw gate projection (fp16)
__device__ __half g_o [(size_t)NROW * HD];     // gated attention output (fp16)
// fp16, transposed weights
__device__ __half g_wT [4 * HD * CDIM];        // [2048][256]  rows: Wq|Wk|Wv|Wg
__device__ __half g_woT[CDIM * HD];            // [256][512]

// ---------------- fp16 mma / ldsm / cp.async helpers ----------------
__device__ __forceinline__ void mma_f16(float* c, const unsigned* a, unsigned b0, unsigned b1) {
    asm volatile(
        "mma.sync.aligned.m16n8k16.row.col.f32.f16.f16.f32 "
        "{%0,%1,%2,%3}, {%4,%5,%6,%7}, {%8,%9}, {%0,%1,%2,%3};"
        : "+f"(c[0]), "+f"(c[1]), "+f"(c[2]), "+f"(c[3])
        : "r"(a[0]), "r"(a[1]), "r"(a[2]), "r"(a[3]), "r"(b0), "r"(b1));
}
__device__ __forceinline__ void ldsm4(unsigned* r, uint32_t addr) {
    asm volatile("ldmatrix.sync.aligned.m8n8.x4.shared.b16 {%0,%1,%2,%3}, [%4];"
                 : "=r"(r[0]), "=r"(r[1]), "=r"(r[2]), "=r"(r[3]) : "r"(addr));
}
__device__ __forceinline__ void ldsm4t(unsigned* r, uint32_t addr) {
    asm volatile("ldmatrix.sync.aligned.m8n8.x4.trans.shared.b16 {%0,%1,%2,%3}, [%4];"
                 : "=r"(r[0]), "=r"(r[1]), "=r"(r[2]), "=r"(r[3]) : "r"(addr));
}
__device__ __forceinline__ void cpa16(uint32_t dst, const void* src) {
    asm volatile("cp.async.cg.shared.global [%0], [%1], 16;" :: "r"(dst), "l"(src));
}
__device__ __forceinline__ void cpa_commit() { asm volatile("cp.async.commit_group;"); }
__device__ __forceinline__ unsigned f22h(float lo, float hi) {
    __half2 h = __floats2half2_rn(lo, hi);
    return *(unsigned*)&h;
}

// ============================= weight transpose->fp16 prepass ==============================
__global__ void wtrans4(const float* __restrict__ Wq, const float* __restrict__ Wk,
                        const float* __restrict__ Wv, const float* __restrict__ Wg,
                        __half* __restrict__ wT) {
    __shared__ float t[32][33];
    const float* W = (blockIdx.z == 0) ? Wq : (blockIdx.z == 1) ? Wk
                   : (blockIdx.z == 2) ? Wv : Wg;
    __half* WT = wT + (size_t)blockIdx.z * HD * CDIM;
    int n0 = blockIdx.x * 32, k0 = blockIdx.y * 32;
    for (int i = threadIdx.y; i < 32; i += 8)
        t[i][threadIdx.x] = W[(size_t)(k0 + i) * HD + n0 + threadIdx.x];
    __syncthreads();
    for (int i = threadIdx.y; i < 32; i += 8)
        WT[(size_t)(n0 + i) * CDIM + k0 + threadIdx.x] = __float2half_rn(t[threadIdx.x][i]);
}

__global__ void wtrans(const float* __restrict__ W, __half* __restrict__ WT, int K, int N) {
    __shared__ float t[32][33];
    int n0 = blockIdx.x * 32, k0 = blockIdx.y * 32;
    for (int i = threadIdx.y; i < 32; i += 8)
        t[i][threadIdx.x] = W[(size_t)(k0 + i) * N + n0 + threadIdx.x];
    __syncthreads();
    for (int i = threadIdx.y; i < 32; i += 8)
        WT[(size_t)(n0 + i) * K + k0 + threadIdx.x] = __float2half_rn(t[threadIdx.x][i]);
}

// ============================= LayerNorm (warp-per-row, fp16 output) ==============================
__global__ void ln_kernel(const float* __restrict__ x,
                          const float* __restrict__ gamma,
                          const float* __restrict__ beta) {
    const int warp = threadIdx.x >> 5;
    const int lane = threadIdx.x & 31;
    const int row  = blockIdx.x * 8 + warp;
    const float* xr = x + (size_t)row * CDIM;

    float4 v0 = *(const float4*)(xr + lane * 4);
    float4 v1 = *(const float4*)(xr + 128 + lane * 4);

    float s = (v0.x + v0.y) + (v0.z + v0.w) + (v1.x + v1.y) + (v1.z + v1.w);
    #pragma unroll
    for (int o = 16; o > 0; o >>= 1) s += __shfl_xor_sync(0xffffffffu, s, o);
    float mean = s * (1.0f / CDIM);

    float d0x = v0.x - mean, d0y = v0.y - mean, d0z = v0.z - mean, d0w = v0.w - mean;
    float d1x = v1.x - mean, d1y = v1.y - mean, d1z = v1.z - mean, d1w = v1.w - mean;
    float s2 = d0x*d0x + d0y*d0y + d0z*d0z + d0w*d0w
             + d1x*d1x + d1y*d1y + d1z*d1z + d1w*d1w;
    #pragma unroll
    for (int o = 16; o > 0; o >>= 1) s2 += __shfl_xor_sync(0xffffffffu, s2, o);
    float rstd = rsqrtf(s2 * (1.0f / CDIM) + 1e-5f);

    float4 ga0 = *(const float4*)(gamma + lane * 4);
    float4 ga1 = *(const float4*)(gamma + 128 + lane * 4);
    float4 be0 = *(const float4*)(beta + lane * 4);
    float4 be1 = *(const float4*)(beta + 128 + lane * 4);

    __half* outr = g_xn + (size_t)row * CDIM;
    uint2 o0, o1;
    o0.x = f22h(d0x * rstd * ga0.x + be0.x, d0y * rstd * ga0.y + be0.y);
    o0.y = f22h(d0z * rstd * ga0.z + be0.z, d0w * rstd * ga0.w + be0.w);
    o1.x = f22h(d1x * rstd * ga1.x + be1.x, d1y * rstd * ga1.y + be1.y);
    o1.y = f22h(d1z * rstd * ga1.z + be1.z, d1w * rstd * ga1.w + be1.w);
    *(uint2*)(outr + lane * 4) = o0;
    *(uint2*)(outr + 128 + lane * 4) = o1;
}

// ============================= FP16 tensor-core GEMM (k64 chunks, 2-stage) ==============================
// 8 warps, block 128x128, warp tile 64x32 (the proven 2-CTA/SM shape), k-chunk 64
// halves, 2-stage cp.async (wait_group 0 at top, refill issued right after the
// barrier so copy kt+1 overlaps compute kt). Half the barriers of the k32 version.
// mode 0: fused QKVG (A=g_xn, BT=g_wT); Q scaled 1/8; all outputs fp16.
// mode 1: output proj (A=g_o, BT=g_woT, C=float out + bias).
#define ASTRH 72                            // 64 k-halves + 8 pad (144B row stride)
#define A_PART_H (128 * ASTRH)              // 9216 halves
#define STAGE_TOT_H (2 * A_PART_H)          // A + B per stage = 18432 halves
#define GEMM_SMEM_BYTES (2 * STAGE_TOT_H * 2)   // 73728 B

__global__ void __launch_bounds__(256, 2) gemm_fp16(
    const __half* __restrict__ BT, const float* __restrict__ bias,
    float* __restrict__ Cext, int mode, int K, int ldc) {

    extern __shared__ __half smem[];

    const int tid  = threadIdx.x;
    const int warp = tid >> 5;
    const int lane = tid & 31;
    const int lg   = lane >> 2;
    const int lq   = lane & 3;
    const int wm   = warp >> 2;
    const int wn   = warp & 3;
    const int m0   = blockIdx.y * 128;
    const int n0bt = blockIdx.x * 128;

    const __half* A;
    __half* Ch = nullptr;
    float*  Cf = nullptr;
    int n0c;
    float scale = 1.0f;
    if (mode == 0) {
        A = g_xn;
        int which = n0bt >> 9;
        if (which == 0)      { Ch = g_q; scale = 0.125f; }
        else if (which == 1) { Ch = g_k; }
        else if (which == 2) { Ch = g_v; }
        else                 { Ch = g_g; }
        n0c = n0bt & 511;
    } else {
        A = g_o;
        Cf = Cext;
        n0c = n0bt;
    }

    const uint32_t smb = (uint32_t)__cvta_generic_to_shared(smem);
    const uint32_t stageB = STAGE_TOT_H * 2u;
    const uint32_t aOff = 0;
    const uint32_t bOff = A_PART_H * 2u;

    const int rA = (lane & 7) + ((lane >> 3) & 1) * 8;
    const int cA = (lane >> 4) & 1;
    const int rB = (lane & 7) + ((lane >> 4) & 1) * 8;
    const int cB = (lane >> 3) & 1;

    float acc[4][4][4];
    #pragma unroll
    for (int i = 0; i < 4; i++)
        #pragma unroll
        for (int j = 0; j < 4; j++)
            #pragma unroll
            for (int e = 0; e < 4; e++) acc[i][j][e] = 0.f;

    const int KT = K >> 6;                  // k-chunks of 64 halves
    const int cprow = tid >> 2;             // 0..63
    const int cpc   = tid & 3;              // chunk 0..3 (and +4)

    // ---- prologue: stage 0 (each thread: 2 rows x 2 chunks per matrix) ----
    #pragma unroll
    for (int i = 0; i < 2; i++) {
        int r = i * 64 + cprow;
        #pragma unroll
        for (int c = 0; c < 2; c++) {
            int ch = cpc + c * 4;
            cpa16(smb + aOff + (uint32_t)(r * ASTRH + ch * 8) * 2,
                  A + (size_t)(m0 + r) * K + ch * 8);
            cpa16(smb + bOff + (uint32_t)(r * ASTRH + ch * 8) * 2,
                  BT + (size_t)(n0bt + r) * K + ch * 8);
        }
    }
    cpa_commit();

    for (int kt = 0; kt < KT; kt++) {
        asm volatile("cp.async.wait_group 0;");
        __syncthreads();

        // refill stage (kt+1)%2 — overlaps the compute below
        if (kt + 1 < KT) {
            uint32_t s = (uint32_t)((kt + 1) & 1) * stageB;
            int koff = (kt + 1) * 64;
            #pragma unroll
            for (int i = 0; i < 2; i++) {
                int r = i * 64 + cprow;
                #pragma unroll
                for (int c = 0; c < 2; c++) {
                    int ch = cpc + c * 4;
                    cpa16(smb + s + aOff + (uint32_t)(r * ASTRH + ch * 8) * 2,
                          A + (size_t)(m0 + r) * K + koff + ch * 8);
                    cpa16(smb + s + bOff + (uint32_t)(r * ASTRH + ch * 8) * 2,
                          BT + (size_t)(n0bt + r) * K + koff + ch * 8);
                }
            }
            cpa_commit();
        }

        const uint32_t aS = smb + (uint32_t)(kt & 1) * stageB + aOff;
        const uint32_t bS = smb + (uint32_t)(kt & 1) * stageB + bOff;
        #pragma unroll
        for (int ks = 0; ks < 4; ks++) {    // four k16 steps per chunk
            unsigned a[4][4], b[2][4];
            #pragma unroll
            for (int mf = 0; mf < 4; mf++) {
                int row = wm * 64 + mf * 16 + rA;
                ldsm4(a[mf], aS + (uint32_t)(row * ASTRH + (ks * 2 + cA) * 8) * 2);
            }
            #pragma unroll
            for (int p = 0; p < 2; p++) {
                int row = wn * 32 + p * 16 + rB;
                ldsm4(b[p], bS + (uint32_t)(row * ASTRH + (ks * 2 + cB) * 8) * 2);
            }
            #pragma unroll
            for (int mf = 0; mf < 4; mf++)
                #pragma unroll
                for (int nf = 0; nf < 4; nf++)
                    mma_f16(acc[mf][nf], a[mf],
                            b[nf >> 1][(nf & 1) * 2], b[nf >> 1][(nf & 1) * 2 + 1]);
        }
    }

    // ---- epilogue ----
    #pragma unroll
    for (int mf = 0; mf < 4; mf++) {
        int row = m0 + wm * 64 + mf * 16 + lg;
        #pragma unroll
        for (int nf = 0; nf < 4; nf++) {
            int col = n0c + wn * 32 + nf * 8 + 2 * lq;
            if (Ch) {
                *(unsigned*)&Ch[(size_t)row * ldc + col] =
                    f22h(acc[mf][nf][0] * scale, acc[mf][nf][1] * scale);
                *(unsigned*)&Ch[(size_t)(row + 8) * ldc + col] =
                    f22h(acc[mf][nf][2] * scale, acc[mf][nf][3] * scale);
            } else {
                float b0 = bias ? bias[col] : 0.f;
                float b1 = bias ? bias[col + 1] : 0.f;
                float2 v0, v1;
                v0.x = acc[mf][nf][0] + b0; v0.y = acc[mf][nf][1] + b1;
                v1.x = acc[mf][nf][2] + b0; v1.y = acc[mf][nf][3] + b1;
                *(float2*)&Cf[(size_t)row * ldc + col] = v0;
                *(float2*)&Cf[(size_t)(row + 8) * ldc + col] = v1;
            }
        }
    }
}

// ============================= FP16 flash attention + gate (register-direct P) ==============================
// 512 threads = 16 warps, 16 query rows/warp. P stays in registers (S C-fragment
// packs directly into the PV A-fragment). No mainloop syncs. V via ldmatrix.trans.
// Single-pass softmax (scores O(6); masked -> exp(-1e9)=0).
#define KSH 72
#define BIAS_OFFH (2 * 256 * KSH)
#define ATTN_SMEM_BYTES (BIAS_OFFH * 2 + 256 * 4)    // ~74.8 KB

__global__ void __launch_bounds__(512, 1) attn_fp16(const float* __restrict__ mask,
                                                    const float* __restrict__ bg) {
    extern __shared__ __half shh[];
    __half* Ks = shh;                    // [256][72]
    __half* Vs = shh + 256 * KSH;        // [256][72]
    float* bias_s = (float*)(shh + BIAS_OFFH);   // [256]

    const int h    = blockIdx.x;
    const int i    = blockIdx.y;
    const int tid  = threadIdx.x;
    const int warp = tid >> 5;
    const int lane = tid & 31;
    const int lq   = lane & 3;
    const int lg   = lane >> 2;
    const size_t base = ((size_t)i * 256) * HD + h * 64;

    const uint32_t shb = (uint32_t)__cvta_generic_to_shared(shh);
    const uint32_t KsB = shb;
    const uint32_t VsB = shb + 256 * KSH * 2u;

    const int rB = (lane & 7) + ((lane >> 4) & 1) * 8;
    const int cB = (lane >> 3) & 1;

    // ---- K,V tile copies (row = 64 halves = 8 uint4) ----
    for (int idx = tid; idx < 256 * 8; idx += 512) {
        int r  = idx >> 3;
        int c8 = (idx & 7) * 8;
        *(uint4*)&Ks[r * KSH + c8] = *(const uint4*)&g_k[base + (size_t)r * HD + c8];
        *(uint4*)&Vs[r * KSH + c8] = *(const uint4*)&g_v[base + (size_t)r * HD + c8];
    }
    if (tid < 256) bias_s[tid] = 1e9f * (mask[i * 256 + tid] - 1.0f);
    __syncthreads();

    // ---- Q fragments (g_q already scaled by 1/8): 4 k16-frags ----
    const int row0 = warp * 16 + lg;
    unsigned qa[4][4];
    #pragma unroll
    for (int kf = 0; kf < 4; kf++) {
        int col = kf * 16 + 2 * lq;
        qa[kf][0] = *(const unsigned*)&g_q[base + (size_t)row0 * HD + col];
        qa[kf][1] = *(const unsigned*)&g_q[base + (size_t)(row0 + 8) * HD + col];
        qa[kf][2] = *(const unsigned*)&g_q[base + (size_t)row0 * HD + col + 8];
        qa[kf][3] = *(const unsigned*)&g_q[base + (size_t)(row0 + 8) * HD + col + 8];
    }

    float oc[8][4];
    #pragma unroll
    for (int nf = 0; nf < 8; nf++)
        #pragma unroll
        for (int e = 0; e < 4; e++) oc[nf][e] = 0.f;

    float l0 = 0.f, l1 = 0.f;

    for (int kc = 0; kc < 256; kc += 64) {
        // ---- S = Q @ K^T chunk [16 x 64] ----
        float sc[8][4];
        #pragma unroll
        for (int nf = 0; nf < 8; nf++)
            sc[nf][0] = sc[nf][1] = sc[nf][2] = sc[nf][3] = 0.f;

        #pragma unroll
        for (int kb = 0; kb < 4; kb++) {          // d16 per step
            unsigned bk[4][4];
            #pragma unroll
            for (int p = 0; p < 4; p++) {         // 16 keys each
                int key = kc + p * 16 + rB;
                ldsm4(bk[p], KsB + (uint32_t)(key * KSH + (kb * 2 + cB) * 8) * 2);
            }
            #pragma unroll
            for (int nf = 0; nf < 8; nf++)
                mma_f16(sc[nf], qa[kb],
                        bk[nf >> 1][(nf & 1) * 2], bk[nf >> 1][(nf & 1) * 2 + 1]);
        }

        // ---- p = exp(s + bias) in-place; accumulate l ----
        #pragma unroll
        for (int nf = 0; nf < 8; nf++) {
            float bb0 = bias_s[kc + nf * 8 + 2 * lq];
            float bb1 = bias_s[kc + nf * 8 + 2 * lq + 1];
            sc[nf][0] = __expf(sc[nf][0] + bb0);
            sc[nf][1] = __expf(sc[nf][1] + bb1);
            sc[nf][2] = __expf(sc[nf][2] + bb0);
            sc[nf][3] = __expf(sc[nf][3] + bb1);
            l0 += sc[nf][0] + sc[nf][1];
            l1 += sc[nf][2] + sc[nf][3];
        }

        // ---- O += P @ V chunk; P packed register-direct into A-frags ----
        #pragma unroll
        for (int kb = 0; kb < 4; kb++) {          // 16 keys per step
            unsigned pa[4];
            pa[0] = f22h(sc[2 * kb][0],     sc[2 * kb][1]);
            pa[1] = f22h(sc[2 * kb][2],     sc[2 * kb][3]);
            pa[2] = f22h(sc[2 * kb + 1][0], sc[2 * kb + 1][1]);
            pa[3] = f22h(sc[2 * kb + 1][2], sc[2 * kb + 1][3]);
            #pragma unroll
            for (int p = 0; p < 4; p++) {         // d16 per step
                unsigned bv[4];
                int keyrow = kc + kb * 16 + rB;
                ldsm4t(bv, VsB + (uint32_t)(keyrow * KSH + (p * 2 + cB) * 8) * 2);
                mma_f16(oc[2 * p],     pa, bv[0], bv[2]);
                mma_f16(oc[2 * p + 1], pa, bv[1], bv[3]);
            }
        }
    }

    // ---- row sums across the 4-lane groups ----
    l0 += __shfl_xor_sync(0xffffffffu, l0, 1);
    l0 += __shfl_xor_sync(0xffffffffu, l0, 2);
    l1 += __shfl_xor_sync(0xffffffffu, l1, 1);
    l1 += __shfl_xor_sync(0xffffffffu, l1, 2);

    float inv0 = 1.0f / l0, inv1 = 1.0f / l1;
    #pragma unroll
    for (int nf = 0; nf < 8; nf++) {
        int d = nf * 8 + 2 * lq;
        float bg0 = bg[h * 64 + d], bg1 = bg[h * 64 + d + 1];
        size_t a0 = base + (size_t)row0 * HD + d;
        size_t a1 = base + (size_t)(row0 + 8) * HD + d;
        __half2 gh0 = *(const __half2*)&g_g[a0];
        __half2 gh1 = *(const __half2*)&g_g[a1];
        float2 gv0 = __half22float2(gh0);
        float2 gv1 = __half22float2(gh1);
        float o0x = oc[nf][0] * inv0 * (1.0f / (1.0f + __expf(-(gv0.x + bg0))));
        float o0y = oc[nf][1] * inv0 * (1.0f / (1.0f + __expf(-(gv0.y + bg1))));
        float o1x = oc[nf][2] * inv1 * (1.0f / (1.0f + __expf(-(gv1.x + bg0))));
        float o1y = oc[nf][3] * inv1 * (1.0f / (1.0f + __expf(-(gv1.y + bg1))));
        *(unsigned*)&g_o[a0] = f22h(o0x, o0y);
        *(unsigned*)&g_o[a1] = f22h(o1x, o1y);
    }
}

// ============================= launch ==============================
extern "C" void kernel_launch(void* const* d_in, const int* in_sizes, int n_in,
                              void* d_out, int out_size) {
    const float* x     = (const float*)d_in[0];
    const float* mask  = (const float*)d_in[1];
    const float* gamma = (const float*)d_in[2];
    const float* beta  = (const float*)d_in[3];
    const float* Wq    = (const float*)d_in[4];
    const float* Wk    = (const float*)d_in[5];
    const float* Wv    = (const float*)d_in[6];
    const float* Wg    = (const float*)d_in[7];
    const float* bg    = (const float*)d_in[8];
    const float* Wo    = (const float*)d_in[9];
    const float* bo    = (const float*)d_in[10];
    float* out = (float*)d_out;

    cudaFuncSetAttribute(attn_fp16, cudaFuncAttributeMaxDynamicSharedMemorySize,
                         ATTN_SMEM_BYTES);   // ~74.8 KB
    cudaFuncSetAttribute(gemm_fp16, cudaFuncAttributeMaxDynamicSharedMemorySize,
                         GEMM_SMEM_BYTES);   // 72 KB (2 CTAs/SM)

    __half* wT;  cudaGetSymbolAddress((void**)&wT,  g_wT);
    __half* woT; cudaGetSymbolAddress((void**)&woT, g_woT);

    // 0) weight transpose->fp16 prepass
    dim3 tt(32, 8);
    wtrans4<<<dim3(HD / 32, CDIM / 32, 4), tt>>>(Wq, Wk, Wv, Wg, wT);
    wtrans<<<dim3(CDIM / 32, HD / 32), tt>>>(Wo, woT, HD, CDIM);

    // 1) LayerNorm (warp-per-row, fp16 out)
    ln_kernel<<<NROW / 8, 256>>>(x, gamma, beta);

    // 2) fused projections: [Q|K|V|G] = xn @ W  (M=65536, N=2048, K=256)
    gemm_fp16<<<dim3(16, 512), 256, GEMM_SMEM_BYTES>>>(wT, nullptr, nullptr, 0, CDIM, HD);

    // 3) attention + gate per (h, i)
    attn_fp16<<<dim3(HDIM, IDIM), 512, ATTN_SMEM_BYTES>>>(mask, bg);

    // 4) output projection: out = o @ Wo + bo  (M=65536, N=256, K=512)
    gemm_fp16<<<dim3(2, 512), 256, GEMM_SMEM_BYTES>>>(woT, bo, out, 1, HD, CDIM);
}